// round 6
// baseline (speedup 1.0000x reference)
#include <cuda_runtime.h>
#include <math.h>

// Problem shapes (fixed)
#define S_LEN 256
#define BATCH 64
#define HSZ   1024
#define H3    3072
#define PLEN  256
#define PSZ   1024
// Output layout: [h_last (64*1024) | hs (256*64*2048) | attn (256*256*64)]
#define HS_OFF   65536
#define ATTN_OFF 33619968
#define NEGV -1000000000.0f

typedef unsigned long long ull;

// ---------------- device scratch (no runtime allocation allowed) -----------
__device__ float g_gi[(size_t)S_LEN * BATCH * H3];       // 201 MB
__device__ float g_q[(size_t)S_LEN * BATCH * PSZ];       //  64 MB
__device__ float g_scores[(size_t)BATCH * S_LEN * PLEN]; //  16 MB
__device__ float g_attnT[(size_t)BATCH * S_LEN * PLEN];  //  16 MB
__device__ float g_ghp[(size_t)8 * BATCH * H3];          // 6.3 MB

// ---------------- packed fp32x2 helpers (Blackwell FFMA2 path) -------------
__device__ __forceinline__ ull pk2(float lo, float hi) {
    ull r;
    asm("mov.b64 %0, {%1, %2};" : "=l"(r) : "f"(lo), "f"(hi));
    return r;
}
__device__ __forceinline__ float2 upk2(ull v) {
    float2 r;
    asm("mov.b64 {%0, %1}, %2;" : "=f"(r.x), "=f"(r.y) : "l"(v));
    return r;
}
__device__ __forceinline__ void f2fma(ull &c, ull a, ull b) {
    asm("fma.rn.f32x2 %0, %1, %2, %0;" : "+l"(c) : "l"(a), "l"(b));
}

// ===========================================================================
// C[M,N] = A[M,K] * B[N,K]^T (+bias). A,B K-contiguous. 128x128 tile, BK=8,
// 256 threads, 8x8 per-thread microtile, fp32x2 accumulation.
// Requires M%128==0, N%128==0, K%8==0. blockIdx.z batches via strides.
// ===========================================================================
__global__ void __launch_bounds__(256, 2) gemm_nt_kernel(
    const float* __restrict__ A, const float* __restrict__ B,
    const float* __restrict__ bias, float* __restrict__ C,
    int K, long long lda, long long ldb, long long ldc,
    long long bsA, long long bsB, long long bsC)
{
    __shared__ __align__(16) float As[8][128];
    __shared__ __align__(16) float Bs[8][128];
    long long bz = blockIdx.z;
    A += bz * bsA; B += bz * bsB; C += bz * bsC;
    int m0 = blockIdx.x * 128, n0 = blockIdx.y * 128;
    int tid = threadIdx.x;
    int lr = tid >> 1, lk = (tid & 1) * 4;
    const float* aP = A + (long long)(m0 + lr) * lda + lk;
    const float* bP = B + (long long)(n0 + lr) * ldb + lk;
    int ty = tid >> 4, tx = tid & 15;

    ull acc[8][4];
#pragma unroll
    for (int i = 0; i < 8; i++)
#pragma unroll
        for (int j = 0; j < 4; j++) acc[i][j] = 0ull;

    for (int k0 = 0; k0 < K; k0 += 8) {
        float4 av = *(const float4*)aP;
        float4 bv = *(const float4*)bP;
        __syncthreads();
        As[lk + 0][lr] = av.x; As[lk + 1][lr] = av.y;
        As[lk + 2][lr] = av.z; As[lk + 3][lr] = av.w;
        Bs[lk + 0][lr] = bv.x; Bs[lk + 1][lr] = bv.y;
        Bs[lk + 2][lr] = bv.z; Bs[lk + 3][lr] = bv.w;
        __syncthreads();
#pragma unroll
        for (int k = 0; k < 8; k++) {
            float4 a0 = *(const float4*)&As[k][ty * 8];
            float4 a1 = *(const float4*)&As[k][ty * 8 + 4];
            ull b0 = *(const ull*)&Bs[k][tx * 8];
            ull b1 = *(const ull*)&Bs[k][tx * 8 + 2];
            ull b2 = *(const ull*)&Bs[k][tx * 8 + 4];
            ull b3 = *(const ull*)&Bs[k][tx * 8 + 6];
            float a[8] = {a0.x, a0.y, a0.z, a0.w, a1.x, a1.y, a1.z, a1.w};
#pragma unroll
            for (int i = 0; i < 8; i++) {
                ull a2 = pk2(a[i], a[i]);
                f2fma(acc[i][0], a2, b0);
                f2fma(acc[i][1], a2, b1);
                f2fma(acc[i][2], a2, b2);
                f2fma(acc[i][3], a2, b3);
            }
        }
        aP += 8; bP += 8;
    }

    float bb[8];
#pragma unroll
    for (int j = 0; j < 8; j++) bb[j] = bias ? bias[n0 + tx * 8 + j] : 0.f;
#pragma unroll
    for (int i = 0; i < 8; i++) {
        float2 p0 = upk2(acc[i][0]), p1 = upk2(acc[i][1]);
        float2 p2 = upk2(acc[i][2]), p3 = upk2(acc[i][3]);
        float4 v0 = make_float4(p0.x + bb[0], p0.y + bb[1], p1.x + bb[2], p1.y + bb[3]);
        float4 v1 = make_float4(p2.x + bb[4], p2.y + bb[5], p3.x + bb[6], p3.y + bb[7]);
        float* cp = C + (long long)(m0 + ty * 8 + i) * ldc + n0 + tx * 8;
        *(float4*)cp = v0;
        *(float4*)(cp + 4) = v1;
    }
}

// ===========================================================================
// C[M,N] = A[M,K] * B[K,N]  (A K-contig rows, B N-contig rows).
// Same tiling. Used for context = attnT @ post.
// ===========================================================================
__global__ void __launch_bounds__(256, 2) gemm_nn_kernel(
    const float* __restrict__ A, const float* __restrict__ B,
    float* __restrict__ C,
    int K, long long lda, long long ldb, long long ldc,
    long long bsA, long long bsB, long long bsC)
{
    __shared__ __align__(16) float As[8][128];
    __shared__ __align__(16) float Bs[8][128];
    long long bz = blockIdx.z;
    A += bz * bsA; B += bz * bsB; C += bz * bsC;
    int m0 = blockIdx.x * 128, n0 = blockIdx.y * 128;
    int tid = threadIdx.x;
    int lr = tid >> 1, lk = (tid & 1) * 4;
    const float* aP = A + (long long)(m0 + lr) * lda + lk;
    int bRow = tid >> 5, bCol = (tid & 31) * 4;
    const float* bP = B + (long long)bRow * ldb + n0 + bCol;
    int ty = tid >> 4, tx = tid & 15;

    ull acc[8][4];
#pragma unroll
    for (int i = 0; i < 8; i++)
#pragma unroll
        for (int j = 0; j < 4; j++) acc[i][j] = 0ull;

    for (int k0 = 0; k0 < K; k0 += 8) {
        float4 av = *(const float4*)aP;
        float4 bv = *(const float4*)bP;
        __syncthreads();
        As[lk + 0][lr] = av.x; As[lk + 1][lr] = av.y;
        As[lk + 2][lr] = av.z; As[lk + 3][lr] = av.w;
        *(float4*)&Bs[bRow][bCol] = bv;
        __syncthreads();
#pragma unroll
        for (int k = 0; k < 8; k++) {
            float4 a0 = *(const float4*)&As[k][ty * 8];
            float4 a1 = *(const float4*)&As[k][ty * 8 + 4];
            ull b0 = *(const ull*)&Bs[k][tx * 8];
            ull b1 = *(const ull*)&Bs[k][tx * 8 + 2];
            ull b2 = *(const ull*)&Bs[k][tx * 8 + 4];
            ull b3 = *(const ull*)&Bs[k][tx * 8 + 6];
            float a[8] = {a0.x, a0.y, a0.z, a0.w, a1.x, a1.y, a1.z, a1.w};
#pragma unroll
            for (int i = 0; i < 8; i++) {
                ull a2 = pk2(a[i], a[i]);
                f2fma(acc[i][0], a2, b0);
                f2fma(acc[i][1], a2, b1);
                f2fma(acc[i][2], a2, b2);
                f2fma(acc[i][3], a2, b3);
            }
        }
        aP += 8; bP += 8 * ldb;
    }

#pragma unroll
    for (int i = 0; i < 8; i++) {
        float2 p0 = upk2(acc[i][0]), p1 = upk2(acc[i][1]);
        float2 p2 = upk2(acc[i][2]), p3 = upk2(acc[i][3]);
        float* cp = C + (long long)(m0 + ty * 8 + i) * ldc + n0 + tx * 8;
        *(float4*)cp = make_float4(p0.x, p0.y, p1.x, p1.y);
        *(float4*)(cp + 4) = make_float4(p2.x, p2.y, p3.x, p3.y);
    }
}

// ===========================================================================
// Per-step split-K GEMM: ghp[ks][b][row] = sum_{k in slice ks}
//   hprev[b][k] * W_hh[row][k].  grid (24 row-tiles of 128, 8 K-slices of 128)
// 256 threads; per-thread: 8 rows (as 4 fp32x2 pairs) x 4 batches.
// ===========================================================================
__global__ void __launch_bounds__(256, 2) gh_split_kernel(
    const float* __restrict__ hprev, long long hstride,
    const float* __restrict__ W, float* __restrict__ ghp)
{
    __shared__ __align__(16) float Hs[16][64];   // [k][b]
    __shared__ __align__(16) float Ws[16][128];  // [k][row]
    int row0 = blockIdx.x * 128;
    int k0 = blockIdx.y * 128;
    int tid = threadIdx.x;
    int tx = tid & 15;   // batch group: b = tx*4 .. +3
    int ty = tid >> 4;   // row group:  rows row0 + ty*8 .. +7

    int lb = tid >> 2, lkq = (tid & 3) * 4;  // h loader: 64 b x 16 k
    int lr = tid >> 1, lkw = (tid & 1) * 8;  // W loader: 128 rows x 16 k

    ull acc[4][4];  // [rowpair][batch]
#pragma unroll
    for (int i = 0; i < 4; i++)
#pragma unroll
        for (int j = 0; j < 4; j++) acc[i][j] = 0ull;

    for (int kt = 0; kt < 8; kt++) {
        float4 hv = *(const float4*)(hprev + (long long)lb * hstride + k0 + kt * 16 + lkq);
        const float* wp = W + (long long)lr * HSZ + (long long)row0 * HSZ + k0 + kt * 16 + lkw;
        float4 w0 = *(const float4*)wp;
        float4 w1 = *(const float4*)(wp + 4);
        __syncthreads();
        Hs[lkq + 0][lb] = hv.x; Hs[lkq + 1][lb] = hv.y;
        Hs[lkq + 2][lb] = hv.z; Hs[lkq + 3][lb] = hv.w;
        Ws[lkw + 0][lr] = w0.x; Ws[lkw + 1][lr] = w0.y;
        Ws[lkw + 2][lr] = w0.z; Ws[lkw + 3][lr] = w0.w;
        Ws[lkw + 4][lr] = w1.x; Ws[lkw + 5][lr] = w1.y;
        Ws[lkw + 6][lr] = w1.z; Ws[lkw + 7][lr] = w1.w;
        __syncthreads();
#pragma unroll
        for (int k = 0; k < 16; k++) {
            float4 hb = *(const float4*)&Hs[k][tx * 4];
            ull w0p = *(const ull*)&Ws[k][ty * 8 + 0];
            ull w1p = *(const ull*)&Ws[k][ty * 8 + 2];
            ull w2p = *(const ull*)&Ws[k][ty * 8 + 4];
            ull w3p = *(const ull*)&Ws[k][ty * 8 + 6];
            float hh[4] = {hb.x, hb.y, hb.z, hb.w};
#pragma unroll
            for (int b4 = 0; b4 < 4; b4++) {
                ull hs2 = pk2(hh[b4], hh[b4]);
                f2fma(acc[0][b4], w0p, hs2);
                f2fma(acc[1][b4], w1p, hs2);
                f2fma(acc[2][b4], w2p, hs2);
                f2fma(acc[3][b4], w3p, hs2);
            }
        }
    }

#pragma unroll
    for (int b4 = 0; b4 < 4; b4++) {
        int b = tx * 4 + b4;
        float2 p0 = upk2(acc[0][b4]), p1 = upk2(acc[1][b4]);
        float2 p2 = upk2(acc[2][b4]), p3 = upk2(acc[3][b4]);
        float* p = ghp + ((long long)blockIdx.y * 64 + b) * H3 + row0 + ty * 8;
        *(float4*)p       = make_float4(p0.x, p0.y, p1.x, p1.y);
        *(float4*)(p + 4) = make_float4(p2.x, p2.y, p3.x, p3.y);
    }
}

// ===========================================================================
// GRU gate kernel: reduce the 8 K-slices, add biases, apply gates + mask,
// write h_new into hs[s] (the output buffer itself).
// grid (4 j-chunks, 64 batches), 256 threads, 1 hidden unit per thread.
// ===========================================================================
__global__ void __launch_bounds__(256) gru_gate_kernel(
    const float* __restrict__ ghp, const float* __restrict__ gi,
    const float* __restrict__ bhh, const float* __restrict__ hprev,
    long long hstride, const int* __restrict__ length, int s,
    float* __restrict__ hout)
{
    int b = blockIdx.y;
    int j = blockIdx.x * 256 + threadIdx.x;
    float gr = bhh[j], gz = bhh[HSZ + j], gn = bhh[2 * HSZ + j];
#pragma unroll
    for (int ks = 0; ks < 8; ks++) {
        const float* p = ghp + ((long long)ks * 64 + b) * H3;
        gr += p[j]; gz += p[HSZ + j]; gn += p[2 * HSZ + j];
    }
    const float* gib = gi + (long long)b * H3;
    float r = 1.f / (1.f + expf(-(gib[j] + gr)));
    float z = 1.f / (1.f + expf(-(gib[HSZ + j] + gz)));
    float n = tanhf(gib[2 * HSZ + j] + r * gn);
    float hp = hprev[(long long)b * hstride + j];
    float keep = (s < length[b]) ? 1.f : 0.f;
    hout[(long long)b * 2048 + j] = (n + z * (hp - n)) * keep;
}

// ===========================================================================
// Masked softmax over l (PLEN) per (s, b). Writes attnT[b][s][l] for the
// context GEMM and attn output [s][l][b].
// ===========================================================================
__global__ void __launch_bounds__(256) softmax_kernel(
    const float* __restrict__ scores, const int* __restrict__ post_length,
    float* __restrict__ attnT, float* __restrict__ attn_out)
{
    __shared__ float sm[256];
    int s = blockIdx.x, b = blockIdx.y, l = threadIdx.x;
    float sc = scores[((long long)b * S_LEN + s) * PLEN + l];
    if (l >= post_length[b]) sc = NEGV;
    sm[l] = sc; __syncthreads();
    for (int o = 128; o > 0; o >>= 1) {
        if (l < o) sm[l] = fmaxf(sm[l], sm[l + o]);
        __syncthreads();
    }
    float mx = sm[0]; __syncthreads();
    float e = expf(sc - mx);
    sm[l] = e; __syncthreads();
    for (int o = 128; o > 0; o >>= 1) {
        if (l < o) sm[l] += sm[l + o];
        __syncthreads();
    }
    float a = e / sm[0];
    attnT[((long long)b * S_LEN + s) * PLEN + l] = a;
    attn_out[(long long)s * (PLEN * BATCH) + (long long)l * BATCH + b] = a;
}

// h_last = hs[255][:, :1024]
__global__ void hlast_kernel(const float* __restrict__ src, float* __restrict__ dst)
{
    int b = blockIdx.x, t = threadIdx.x;
    float4 v = *(const float4*)(src + (long long)b * 2048 + t * 4);
    *(float4*)(dst + (long long)b * 1024 + t * 4) = v;
}

// ===========================================================================
extern "C" void kernel_launch(void* const* d_in, const int* in_sizes, int n_in,
                              void* d_out, int out_size)
{
    const float* incoming = (const float*)d_in[0];   // [256,64,1024]
    const float* post     = (const float*)d_in[1];   // [256,64,1024]
    const float* h_init   = (const float*)d_in[2];   // [1,1,1024]
    const float* W_ih     = (const float*)d_in[3];   // [3072,1024]
    const float* W_hh     = (const float*)d_in[4];   // [3072,1024]
    const float* b_ih     = (const float*)d_in[5];   // [3072]
    const float* b_hh     = (const float*)d_in[6];   // [3072]
    const float* Wq       = (const float*)d_in[7];   // [1024,1024]
    const float* bq       = (const float*)d_in[8];   // [1024]
    const int*   length   = (const int*)d_in[9];     // [64]
    const int*   plen     = (const int*)d_in[10];    // [64]
    float* out = (float*)d_out;

    float *gi, *q, *scores, *attnT, *ghp;
    cudaGetSymbolAddress((void**)&gi,     g_gi);
    cudaGetSymbolAddress((void**)&q,      g_q);
    cudaGetSymbolAddress((void**)&scores, g_scores);
    cudaGetSymbolAddress((void**)&attnT,  g_attnT);
    cudaGetSymbolAddress((void**)&ghp,    g_ghp);

    // 1) gi = incoming @ W_ih^T + b_ih : [16384, 3072], K=1024
    gemm_nt_kernel<<<dim3(128, 24, 1), 256>>>(
        incoming, W_ih, b_ih, gi, 1024, 1024, 1024, 3072, 0, 0, 0);

    // 2) recurrence: 256 steps x (split-K gh GEMM + gate/reduce)
    for (int s = 0; s < S_LEN; s++) {
        const float* hp = (s == 0) ? h_init
                                   : out + HS_OFF + (long long)(s - 1) * BATCH * 2048;
        long long hstr = (s == 0) ? 0 : 2048;
        gh_split_kernel<<<dim3(24, 8), 256>>>(hp, hstr, W_hh, ghp);
        gru_gate_kernel<<<dim3(4, 64), 256>>>(
            ghp, gi + (long long)s * BATCH * H3, b_hh, hp, hstr, length, s,
            out + HS_OFF + (long long)s * BATCH * 2048);
    }

    // 3) queries = hs_h @ Wq^T + bq : [16384, 1024], A stride 2048
    gemm_nt_kernel<<<dim3(128, 8, 1), 256>>>(
        out + HS_OFF, Wq, bq, q, 1024, 2048, 1024, 1024, 0, 0, 0);

    // 4) scores[b][s][l] = q[s,b,:] . post[l,b,:]  (batched over b)
    gemm_nt_kernel<<<dim3(2, 2, 64), 256>>>(
        q, post, (const float*)0, scores, 1024,
        (long long)BATCH * PSZ, (long long)BATCH * PSZ, PLEN,
        PSZ, PSZ, (long long)S_LEN * PLEN);

    // 5) masked softmax over l; writes attnT and the attn output block
    softmax_kernel<<<dim3(256, 64), 256>>>(scores, plen, attnT, out + ATTN_OFF);

    // 6) context[s][b][p] = attnT[b][s][:] @ post[:,b,:]  (batched over b)
    gemm_nn_kernel<<<dim3(2, 8, 64), 256>>>(
        attnT, post, out + HS_OFF + 1024, PLEN,
        PLEN, (long long)BATCH * PSZ, (long long)BATCH * 2048,
        (long long)S_LEN * PLEN, PSZ, 2048);

    // 7) h_last = hs[255, :, :1024]
    hlast_kernel<<<64, 256>>>(out + HS_OFF + (long long)255 * BATCH * 2048, out);
}

// round 8
// speedup vs baseline: 1.0029x; 1.0029x over previous
#include <cuda_runtime.h>
#include <math.h>

// Problem shapes (fixed)
#define S_LEN 256
#define BATCH 64
#define HSZ   1024
#define H3    3072
#define PLEN  256
#define PSZ   1024
// Output layout: [h_last (64*1024) | hs (256*64*2048) | attn (256*256*64)]
#define HS_OFF   65536
#define ATTN_OFF 33619968
#define NEGV -1000000000.0f

typedef unsigned long long ull;

// ---------------- device scratch (no runtime allocation allowed) -----------
__device__ float g_gi[(size_t)S_LEN * BATCH * H3];       // 201 MB
__device__ float g_q[(size_t)S_LEN * BATCH * PSZ];       //  64 MB
__device__ float g_scores[(size_t)BATCH * S_LEN * PLEN]; //  16 MB
__device__ float g_attnT[(size_t)BATCH * S_LEN * PLEN];  //  16 MB
__device__ float g_ghp[(size_t)8 * BATCH * H3];          // 6.3 MB

// ---------------- packed fp32x2 helpers (Blackwell FFMA2 path) -------------
__device__ __forceinline__ ull pk2(float lo, float hi) {
    ull r;
    asm("mov.b64 %0, {%1, %2};" : "=l"(r) : "f"(lo), "f"(hi));
    return r;
}
__device__ __forceinline__ float2 upk2(ull v) {
    float2 r;
    asm("mov.b64 {%0, %1}, %2;" : "=f"(r.x), "=f"(r.y) : "l"(v));
    return r;
}
__device__ __forceinline__ void f2fma(ull &c, ull a, ull b) {
    asm("fma.rn.f32x2 %0, %1, %2, %0;" : "+l"(c) : "l"(a), "l"(b));
}

// ===========================================================================
// C[M,N] = A[M,K] * B[N,K]^T (+bias). A,B K-contiguous. 128x128 tile, BK=8,
// 256 threads, 8x8 per-thread microtile, fp32x2 accumulation.
// Requires M%128==0, N%128==0, K%8==0. blockIdx.z batches via strides.
// ===========================================================================
__global__ void __launch_bounds__(256, 2) gemm_nt_kernel(
    const float* __restrict__ A, const float* __restrict__ B,
    const float* __restrict__ bias, float* __restrict__ C,
    int K, long long lda, long long ldb, long long ldc,
    long long bsA, long long bsB, long long bsC)
{
    __shared__ __align__(16) float As[8][128];
    __shared__ __align__(16) float Bs[8][128];
    long long bz = blockIdx.z;
    A += bz * bsA; B += bz * bsB; C += bz * bsC;
    int m0 = blockIdx.x * 128, n0 = blockIdx.y * 128;
    int tid = threadIdx.x;
    int lr = tid >> 1, lk = (tid & 1) * 4;
    const float* aP = A + (long long)(m0 + lr) * lda + lk;
    const float* bP = B + (long long)(n0 + lr) * ldb + lk;
    int ty = tid >> 4, tx = tid & 15;

    ull acc[8][4];
#pragma unroll
    for (int i = 0; i < 8; i++)
#pragma unroll
        for (int j = 0; j < 4; j++) acc[i][j] = 0ull;

    for (int k0 = 0; k0 < K; k0 += 8) {
        float4 av = *(const float4*)aP;
        float4 bv = *(const float4*)bP;
        __syncthreads();
        As[lk + 0][lr] = av.x; As[lk + 1][lr] = av.y;
        As[lk + 2][lr] = av.z; As[lk + 3][lr] = av.w;
        Bs[lk + 0][lr] = bv.x; Bs[lk + 1][lr] = bv.y;
        Bs[lk + 2][lr] = bv.z; Bs[lk + 3][lr] = bv.w;
        __syncthreads();
#pragma unroll
        for (int k = 0; k < 8; k++) {
            float4 a0 = *(const float4*)&As[k][ty * 8];
            float4 a1 = *(const float4*)&As[k][ty * 8 + 4];
            ull b0 = *(const ull*)&Bs[k][tx * 8];
            ull b1 = *(const ull*)&Bs[k][tx * 8 + 2];
            ull b2 = *(const ull*)&Bs[k][tx * 8 + 4];
            ull b3 = *(const ull*)&Bs[k][tx * 8 + 6];
            float a[8] = {a0.x, a0.y, a0.z, a0.w, a1.x, a1.y, a1.z, a1.w};
#pragma unroll
            for (int i = 0; i < 8; i++) {
                ull a2 = pk2(a[i], a[i]);
                f2fma(acc[i][0], a2, b0);
                f2fma(acc[i][1], a2, b1);
                f2fma(acc[i][2], a2, b2);
                f2fma(acc[i][3], a2, b3);
            }
        }
        aP += 8; bP += 8;
    }

    float bb[8];
#pragma unroll
    for (int j = 0; j < 8; j++) bb[j] = bias ? bias[n0 + tx * 8 + j] : 0.f;
#pragma unroll
    for (int i = 0; i < 8; i++) {
        float2 p0 = upk2(acc[i][0]), p1 = upk2(acc[i][1]);
        float2 p2 = upk2(acc[i][2]), p3 = upk2(acc[i][3]);
        float4 v0 = make_float4(p0.x + bb[0], p0.y + bb[1], p1.x + bb[2], p1.y + bb[3]);
        float4 v1 = make_float4(p2.x + bb[4], p2.y + bb[5], p3.x + bb[6], p3.y + bb[7]);
        float* cp = C + (long long)(m0 + ty * 8 + i) * ldc + n0 + tx * 8;
        *(float4*)cp = v0;
        *(float4*)(cp + 4) = v1;
    }
}

// ===========================================================================
// C[M,N] = A[M,K] * B[K,N]  (A K-contig rows, B N-contig rows).
// Same tiling. Used for context = attnT @ post.
// ===========================================================================
__global__ void __launch_bounds__(256, 2) gemm_nn_kernel(
    const float* __restrict__ A, const float* __restrict__ B,
    float* __restrict__ C,
    int K, long long lda, long long ldb, long long ldc,
    long long bsA, long long bsB, long long bsC)
{
    __shared__ __align__(16) float As[8][128];
    __shared__ __align__(16) float Bs[8][128];
    long long bz = blockIdx.z;
    A += bz * bsA; B += bz * bsB; C += bz * bsC;
    int m0 = blockIdx.x * 128, n0 = blockIdx.y * 128;
    int tid = threadIdx.x;
    int lr = tid >> 1, lk = (tid & 1) * 4;
    const float* aP = A + (long long)(m0 + lr) * lda + lk;
    int bRow = tid >> 5, bCol = (tid & 31) * 4;
    const float* bP = B + (long long)bRow * ldb + n0 + bCol;
    int ty = tid >> 4, tx = tid & 15;

    ull acc[8][4];
#pragma unroll
    for (int i = 0; i < 8; i++)
#pragma unroll
        for (int j = 0; j < 4; j++) acc[i][j] = 0ull;

    for (int k0 = 0; k0 < K; k0 += 8) {
        float4 av = *(const float4*)aP;
        float4 bv = *(const float4*)bP;
        __syncthreads();
        As[lk + 0][lr] = av.x; As[lk + 1][lr] = av.y;
        As[lk + 2][lr] = av.z; As[lk + 3][lr] = av.w;
        *(float4*)&Bs[bRow][bCol] = bv;
        __syncthreads();
#pragma unroll
        for (int k = 0; k < 8; k++) {
            float4 a0 = *(const float4*)&As[k][ty * 8];
            float4 a1 = *(const float4*)&As[k][ty * 8 + 4];
            ull b0 = *(const ull*)&Bs[k][tx * 8];
            ull b1 = *(const ull*)&Bs[k][tx * 8 + 2];
            ull b2 = *(const ull*)&Bs[k][tx * 8 + 4];
            ull b3 = *(const ull*)&Bs[k][tx * 8 + 6];
            float a[8] = {a0.x, a0.y, a0.z, a0.w, a1.x, a1.y, a1.z, a1.w};
#pragma unroll
            for (int i = 0; i < 8; i++) {
                ull a2 = pk2(a[i], a[i]);
                f2fma(acc[i][0], a2, b0);
                f2fma(acc[i][1], a2, b1);
                f2fma(acc[i][2], a2, b2);
                f2fma(acc[i][3], a2, b3);
            }
        }
        aP += 8; bP += 8 * ldb;
    }

#pragma unroll
    for (int i = 0; i < 8; i++) {
        float2 p0 = upk2(acc[i][0]), p1 = upk2(acc[i][1]);
        float2 p2 = upk2(acc[i][2]), p3 = upk2(acc[i][3]);
        float* cp = C + (long long)(m0 + ty * 8 + i) * ldc + n0 + tx * 8;
        *(float4*)cp = make_float4(p0.x, p0.y, p1.x, p1.y);
        *(float4*)(cp + 4) = make_float4(p2.x, p2.y, p3.x, p3.y);
    }
}

// ===========================================================================
// Per-step split-K GEMM: ghp[ks][b][row] = sum_{k in slice ks}
//   hprev[b][k] * W_hh[row][k].  grid (24 row-tiles of 128, 8 K-slices of 128)
// 256 threads; per-thread: 8 rows (as 4 fp32x2 pairs) x 4 batches.
// ===========================================================================
__global__ void __launch_bounds__(256, 2) gh_split_kernel(
    const float* __restrict__ hprev, long long hstride,
    const float* __restrict__ W, float* __restrict__ ghp)
{
    __shared__ __align__(16) float Hs[16][64];   // [k][b]
    __shared__ __align__(16) float Ws[16][128];  // [k][row]
    int row0 = blockIdx.x * 128;
    int k0 = blockIdx.y * 128;
    int tid = threadIdx.x;
    int tx = tid & 15;   // batch group: b = tx*4 .. +3
    int ty = tid >> 4;   // row group:  rows row0 + ty*8 .. +7

    int lb = tid >> 2, lkq = (tid & 3) * 4;  // h loader: 64 b x 16 k
    int lr = tid >> 1, lkw = (tid & 1) * 8;  // W loader: 128 rows x 16 k

    ull acc[4][4];  // [rowpair][batch]
#pragma unroll
    for (int i = 0; i < 4; i++)
#pragma unroll
        for (int j = 0; j < 4; j++) acc[i][j] = 0ull;

    for (int kt = 0; kt < 8; kt++) {
        float4 hv = *(const float4*)(hprev + (long long)lb * hstride + k0 + kt * 16 + lkq);
        const float* wp = W + (long long)lr * HSZ + (long long)row0 * HSZ + k0 + kt * 16 + lkw;
        float4 w0 = *(const float4*)wp;
        float4 w1 = *(const float4*)(wp + 4);
        __syncthreads();
        Hs[lkq + 0][lb] = hv.x; Hs[lkq + 1][lb] = hv.y;
        Hs[lkq + 2][lb] = hv.z; Hs[lkq + 3][lb] = hv.w;
        Ws[lkw + 0][lr] = w0.x; Ws[lkw + 1][lr] = w0.y;
        Ws[lkw + 2][lr] = w0.z; Ws[lkw + 3][lr] = w0.w;
        Ws[lkw + 4][lr] = w1.x; Ws[lkw + 5][lr] = w1.y;
        Ws[lkw + 6][lr] = w1.z; Ws[lkw + 7][lr] = w1.w;
        __syncthreads();
#pragma unroll
        for (int k = 0; k < 16; k++) {
            float4 hb = *(const float4*)&Hs[k][tx * 4];
            ull w0p = *(const ull*)&Ws[k][ty * 8 + 0];
            ull w1p = *(const ull*)&Ws[k][ty * 8 + 2];
            ull w2p = *(const ull*)&Ws[k][ty * 8 + 4];
            ull w3p = *(const ull*)&Ws[k][ty * 8 + 6];
            float hh[4] = {hb.x, hb.y, hb.z, hb.w};
#pragma unroll
            for (int b4 = 0; b4 < 4; b4++) {
                ull hs2 = pk2(hh[b4], hh[b4]);
                f2fma(acc[0][b4], w0p, hs2);
                f2fma(acc[1][b4], w1p, hs2);
                f2fma(acc[2][b4], w2p, hs2);
                f2fma(acc[3][b4], w3p, hs2);
            }
        }
    }

#pragma unroll
    for (int b4 = 0; b4 < 4; b4++) {
        int b = tx * 4 + b4;
        float2 p0 = upk2(acc[0][b4]), p1 = upk2(acc[1][b4]);
        float2 p2 = upk2(acc[2][b4]), p3 = upk2(acc[3][b4]);
        float* p = ghp + ((long long)blockIdx.y * 64 + b) * H3 + row0 + ty * 8;
        *(float4*)p       = make_float4(p0.x, p0.y, p1.x, p1.y);
        *(float4*)(p + 4) = make_float4(p2.x, p2.y, p3.x, p3.y);
    }
}

// ===========================================================================
// GRU gate kernel: reduce the 8 K-slices, add biases, apply gates + mask,
// write h_new into hs[s] (the output buffer itself).
// grid (4 j-chunks, 64 batches), 256 threads, 1 hidden unit per thread.
// ===========================================================================
__global__ void __launch_bounds__(256) gru_gate_kernel(
    const float* __restrict__ ghp, const float* __restrict__ gi,
    const float* __restrict__ bhh, const float* __restrict__ hprev,
    long long hstride, const int* __restrict__ length, int s,
    float* __restrict__ hout)
{
    int b = blockIdx.y;
    int j = blockIdx.x * 256 + threadIdx.x;
    float gr = bhh[j], gz = bhh[HSZ + j], gn = bhh[2 * HSZ + j];
#pragma unroll
    for (int ks = 0; ks < 8; ks++) {
        const float* p = ghp + ((long long)ks * 64 + b) * H3;
        gr += p[j]; gz += p[HSZ + j]; gn += p[2 * HSZ + j];
    }
    const float* gib = gi + (long long)b * H3;
    float r = 1.f / (1.f + expf(-(gib[j] + gr)));
    float z = 1.f / (1.f + expf(-(gib[HSZ + j] + gz)));
    float n = tanhf(gib[2 * HSZ + j] + r * gn);
    float hp = hprev[(long long)b * hstride + j];
    float keep = (s < length[b]) ? 1.f : 0.f;
    hout[(long long)b * 2048 + j] = (n + z * (hp - n)) * keep;
}

// ===========================================================================
// Masked softmax over l (PLEN) per (s, b). Writes attnT[b][s][l] for the
// context GEMM and attn output [s][l][b].
// ===========================================================================
__global__ void __launch_bounds__(256) softmax_kernel(
    const float* __restrict__ scores, const int* __restrict__ post_length,
    float* __restrict__ attnT, float* __restrict__ attn_out)
{
    __shared__ float sm[256];
    int s = blockIdx.x, b = blockIdx.y, l = threadIdx.x;
    float sc = scores[((long long)b * S_LEN + s) * PLEN + l];
    if (l >= post_length[b]) sc = NEGV;
    sm[l] = sc; __syncthreads();
    for (int o = 128; o > 0; o >>= 1) {
        if (l < o) sm[l] = fmaxf(sm[l], sm[l + o]);
        __syncthreads();
    }
    float mx = sm[0]; __syncthreads();
    float e = expf(sc - mx);
    sm[l] = e; __syncthreads();
    for (int o = 128; o > 0; o >>= 1) {
        if (l < o) sm[l] += sm[l + o];
        __syncthreads();
    }
    float a = e / sm[0];
    attnT[((long long)b * S_LEN + s) * PLEN + l] = a;
    attn_out[(long long)s * (PLEN * BATCH) + (long long)l * BATCH + b] = a;
}

// h_last = hs[255][:, :1024]
__global__ void hlast_kernel(const float* __restrict__ src, float* __restrict__ dst)
{
    int b = blockIdx.x, t = threadIdx.x;
    float4 v = *(const float4*)(src + (long long)b * 2048 + t * 4);
    *(float4*)(dst + (long long)b * 1024 + t * 4) = v;
}

// ===========================================================================
extern "C" void kernel_launch(void* const* d_in, const int* in_sizes, int n_in,
                              void* d_out, int out_size)
{
    const float* incoming = (const float*)d_in[0];   // [256,64,1024]
    const float* post     = (const float*)d_in[1];   // [256,64,1024]
    const float* h_init   = (const float*)d_in[2];   // [1,1,1024]
    const float* W_ih     = (const float*)d_in[3];   // [3072,1024]
    const float* W_hh     = (const float*)d_in[4];   // [3072,1024]
    const float* b_ih     = (const float*)d_in[5];   // [3072]
    const float* b_hh     = (const float*)d_in[6];   // [3072]
    const float* Wq       = (const float*)d_in[7];   // [1024,1024]
    const float* bq       = (const float*)d_in[8];   // [1024]
    const int*   length   = (const int*)d_in[9];     // [64]
    const int*   plen     = (const int*)d_in[10];    // [64]
    float* out = (float*)d_out;

    float *gi, *q, *scores, *attnT, *ghp;
    cudaGetSymbolAddress((void**)&gi,     g_gi);
    cudaGetSymbolAddress((void**)&q,      g_q);
    cudaGetSymbolAddress((void**)&scores, g_scores);
    cudaGetSymbolAddress((void**)&attnT,  g_attnT);
    cudaGetSymbolAddress((void**)&ghp,    g_ghp);

    // 1) gi = incoming @ W_ih^T + b_ih : [16384, 3072], K=1024
    gemm_nt_kernel<<<dim3(128, 24, 1), 256>>>(
        incoming, W_ih, b_ih, gi, 1024, 1024, 1024, 3072, 0, 0, 0);

    // 2) recurrence: 256 steps x (split-K gh GEMM + gate/reduce)
    for (int s = 0; s < S_LEN; s++) {
        const float* hp = (s == 0) ? h_init
                                   : out + HS_OFF + (long long)(s - 1) * BATCH * 2048;
        long long hstr = (s == 0) ? 0 : 2048;
        gh_split_kernel<<<dim3(24, 8), 256>>>(hp, hstr, W_hh, ghp);
        gru_gate_kernel<<<dim3(4, 64), 256>>>(
            ghp, gi + (long long)s * BATCH * H3, b_hh, hp, hstr, length, s,
            out + HS_OFF + (long long)s * BATCH * 2048);
    }

    // 3) queries = hs_h @ Wq^T + bq : [16384, 1024], A stride 2048
    gemm_nt_kernel<<<dim3(128, 8, 1), 256>>>(
        out + HS_OFF, Wq, bq, q, 1024, 2048, 1024, 1024, 0, 0, 0);

    // 4) scores[b][s][l] = q[s,b,:] . post[l,b,:]  (batched over b)
    gemm_nt_kernel<<<dim3(2, 2, 64), 256>>>(
        q, post, (const float*)0, scores, 1024,
        (long long)BATCH * PSZ, (long long)BATCH * PSZ, PLEN,
        PSZ, PSZ, (long long)S_LEN * PLEN);

    // 5) masked softmax over l; writes attnT and the attn output block
    softmax_kernel<<<dim3(256, 64), 256>>>(scores, plen, attnT, out + ATTN_OFF);

    // 6) context[s][b][p] = attnT[b][s][:] @ post[:,b,:]  (batched over b)
    gemm_nn_kernel<<<dim3(2, 8, 64), 256>>>(
        attnT, post, out + HS_OFF + 1024, PLEN,
        PLEN, (long long)BATCH * PSZ, (long long)BATCH * 2048,
        (long long)S_LEN * PLEN, PSZ, 2048);

    // 7) h_last = hs[255, :, :1024]
    hlast_kernel<<<64, 256>>>(out + HS_OFF + (long long)255 * BATCH * 2048, out);
}